// round 11
// baseline (speedup 1.0000x reference)
#include <cuda_runtime.h>
#include <cuda_fp16.h>
#include <cstdint>

#define NN 20000
#define MM 64
#define WL 8
#define NPAIRS (MM*NN*WL)      /* 10,240,000 pairs per X tensor */
#define NPB 8                  /* n's per chunk */
#define NCHUNK (NN/NPB)        /* 2500 */
#define NBLK 148               /* one block per SM */
#define NT 1024                /* 16 producer + 16 consumer warps */
#define NPROD 512
#define NSTG 4

/* ---- stage: F1h [64][9] uint2 (4608 B) + F2f [8][65] float4 (8320 B) ---- */
#define STG_F2    4608
#define STG_BYTES 12928

/* ---- shared memory layout (bytes) ---- */
#define OFF_STG   (NN*8)                      /* 160000 : table first          */
#define OFF_PIP   (OFF_STG + NSTG*STG_BYTES)  /* 211712 : piP half2[32*64]     */
#define OFF_P12   (OFF_PIP + 8192)            /* 219904 : pi1, pi2             */
#define OFF_RED   (OFF_P12 + 512)             /* 220416 : float4[4][8][2]      */
#define OFF_CTL   (OFF_RED + 1024)            /* 221440 : hdr[4] + 8 mbarriers */
#define SMEM_TOTAL (OFF_CTL + 96)             /* 221536 */

typedef unsigned long long ull;

// ---------------- device scratch (static) ------------------------------------
__device__ unsigned g_cx1[NPAIRS];   // packed (i0 | i1<<16)
__device__ unsigned g_cx2[NPAIRS];
__device__ uint2    g_tabB[NN];      // intermediate a after iter 0 (half x 4 batches)
__device__ int      g_tick[2] = {0, 0};

// ---------------- small helpers ----------------------------------------------
__device__ __forceinline__ unsigned s2u(const void* p) {
    return (unsigned)__cvta_generic_to_shared(p);
}
__device__ __forceinline__ void mbar_init(unsigned a, unsigned cnt) {
    asm volatile("mbarrier.init.shared.b64 [%0], %1;" :: "r"(a), "r"(cnt) : "memory");
}
__device__ __forceinline__ void mbar_arrive(unsigned a) {
    asm volatile("mbarrier.arrive.release.cta.shared::cta.b64 _, [%0];" :: "r"(a) : "memory");
}
__device__ __forceinline__ void mbar_wait(unsigned a, unsigned parity) {
    asm volatile(
        "{\n\t.reg .pred P;\n\t"
        "WL_%=:\n\t"
        "mbarrier.try_wait.parity.acquire.cta.shared::cta.b64 P, [%0], %1, 0x989680;\n\t"
        "@P bra.uni WD_%=;\n\t"
        "bra.uni WL_%=;\n\t"
        "WD_%=:\n\t}"
        :: "r"(a), "r"(parity) : "memory");
}
__device__ __forceinline__ ull pack2(float lo, float hi) {
    ull r; asm("mov.b64 %0, {%1, %2};" : "=l"(r) : "f"(lo), "f"(hi)); return r;
}
__device__ __forceinline__ float2 unpack2(ull v) {
    float2 f; asm("mov.b64 {%0, %1}, %2;" : "=f"(f.x), "=f"(f.y) : "l"(v)); return f;
}
__device__ __forceinline__ void fma2(ull& d, ull a, ull b) {
    asm("fma.rn.f32x2 %0, %1, %2, %0;" : "+l"(d) : "l"(a), "l"(b));
}
// gather: 8 independent products, max tree
__device__ __forceinline__ void gath8(const unsigned* pk, const uint2* __restrict__ tab,
                                      __half2& ga, __half2& gb) {
    __half2 px[8], py[8];
    #pragma unroll
    for (int w = 0; w < 8; w++) {
        uint2 A = tab[pk[w] & 0xFFFFu];
        uint2 B = tab[pk[w] >> 16];
        px[w] = __hmul2(*(__half2*)&A.x, *(__half2*)&B.x);
        py[w] = __hmul2(*(__half2*)&A.y, *(__half2*)&B.y);
    }
    #pragma unroll
    for (int s = 4; s > 0; s >>= 1)
        #pragma unroll
        for (int w = 0; w < s; w++) {
            px[w] = __hmax2(px[w], px[w + s]);
            py[w] = __hmax2(py[w], py[w + s]);
        }
    ga = px[0]; gb = py[0];
}

// ---------------- main iteration kernel --------------------------------------
template<int ITER>
__global__ void __launch_bounds__(NT, 1) k_iter(const float* __restrict__ a0,
                                                const float* __restrict__ Wm,
                                                const void* __restrict__ x1,
                                                const void* __restrict__ x2,
                                                float* __restrict__ out) {
    extern __shared__ char smem[];
    uint2*    tabh = (uint2*)smem;                    // [NN]
    __half2*  piPh = (__half2*)(smem + OFF_PIP);      // [32*64]
    float*    pi1s = (float*) (smem + OFF_P12);
    float*    pi2s = pi1s + MM;
    float4*   red4 = (float4*)(smem + OFF_RED);       // [4][8][2]
    float*    redf = (float*) (smem + OFF_RED);
    volatile int* hdr = (volatile int*)(smem + OFF_CTL);  // [4]
    const unsigned mb_full  = s2u(smem + OFF_CTL + 16);   // 4 x 8B
    const unsigned mb_empty = s2u(smem + OFF_CTL + 48);   // 4 x 8B

    const int tid  = threadIdx.x;
    const int warp = tid >> 5, lane = tid & 31;

    // reset the OTHER iter's ticket for the next launch/replay
    if (blockIdx.x == 0 && tid == 0) g_tick[ITER ^ 1] = 0;
    if (tid < NSTG) {
        mbar_init(mb_full  + 8*tid, NPROD);
        mbar_init(mb_empty + 8*tid, NT - NPROD);
    }

    // ===== preamble (all threads): a-table =====
    if (ITER == 0) {
        for (int i = tid; i < NN; i += NT) {
            __half2 h01 = __floats2half2_rn(__ldg(a0 + i),        __ldg(a0 + NN + i));
            __half2 h23 = __floats2half2_rn(__ldg(a0 + 2*NN + i), __ldg(a0 + 3*NN + i));
            tabh[i] = make_uint2(*(unsigned*)&h01, *(unsigned*)&h23);
        }
    } else {
        for (int i = tid; i < NN; i += NT) tabh[i] = g_tabB[i];
    }

    // ===== preamble: softmax over 64x64 W (scratch = stage area, pre-roles) =====
    {
        float* sp = (float*)(smem + OFF_STG);
        float v4[4];
        float lm = -1e30f;
        #pragma unroll
        for (int t = 0; t < 4; t++) {
            float v = __ldg(Wm + tid + t*NT);
            v4[t] = v;
            lm = fmaxf(lm, v);
        }
        #pragma unroll
        for (int off = 16; off > 0; off >>= 1)
            lm = fmaxf(lm, __shfl_xor_sync(0xFFFFFFFFu, lm, off));
        if (lane == 0) redf[warp] = lm;
        __syncthreads();
        float m = -1e30f;
        #pragma unroll
        for (int w = 0; w < 32; w++) m = fmaxf(m, redf[w]);
        __syncthreads();
        float ls = 0.f;
        #pragma unroll
        for (int t = 0; t < 4; t++) {
            float e = expf(v4[t] - m);
            sp[tid + t*NT] = e;
            ls += e;
        }
        #pragma unroll
        for (int off = 16; off > 0; off >>= 1)
            ls += __shfl_xor_sync(0xFFFFFFFFu, ls, off);
        if (lane == 0) redf[32 + warp] = ls;
        __syncthreads();
        float tot = 0.f;
        #pragma unroll
        for (int w = 0; w < 32; w++) tot += redf[32 + w];
        const float inv = 1.f / tot;

        for (int i = tid; i < 2048; i += NT) {
            int kp = i >> 6, j = i & 63;
            piPh[i] = __floats2half2_rn(sp[j*MM + 2*kp] * inv, sp[j*MM + 2*kp + 1] * inv);
        }
        if (tid < MM) {
            float s = 0.f;
            #pragma unroll 16
            for (int k = 0; k < MM; k++) s += sp[tid*MM + k];
            pi1s[tid] = s * inv;
        } else if (tid < 2*MM) {
            int k = tid - MM;
            float s = 0.f;
            #pragma unroll 16
            for (int j = 0; j < MM; j++) s += sp[j*MM + k];
            pi2s[k] = s * inv;
        }
    }

    // ===== preamble: dtype probe (iter 0 only) =====
    int is64 = 0;
    if (ITER == 0) {
        const unsigned* x1u = (const unsigned*)x1;
        int nz = (x1u[2*tid + 1] != 0u) | (x1u[2*(tid + NT) + 1] != 0u);
        is64 = !__syncthreads_or(nz);
    }
    __syncthreads();   // scratch dead; tab/piP/pi/mbar visible to all

    int* tick = &g_tick[ITER];

    if (tid < NPROD) {
        // ============ PRODUCER: one (j, nl) task per thread per chunk ============
        const int j  = tid >> 3;           // 0..63
        const int nl = tid & 7;            // 0..7
        for (int i = 0; ; i++) {
            const int s = i & 3, ks = i >> 2;
            if (i >= NSTG) mbar_wait(mb_empty + 8*s, (ks - 1) & 1);
            if (tid == 0) hdr[s] = atomicAdd(tick, 1);
            asm volatile("bar.sync 1, %0;" :: "n"(NPROD) : "memory");
            const int chunk = hdr[s];
            if (chunk >= NCHUNK) { mbar_arrive(mb_full + 8*s); break; }
            const int n0 = chunk * NPB;
            uint2*  F1h = (uint2*) (smem + OFF_STG + s*STG_BYTES);
            float4* F2f = (float4*)(smem + OFF_STG + s*STG_BYTES + STG_F2);

            const size_t pb = ((size_t)j * NN + n0 + nl) * WL;
            unsigned pk1[8], pk2[8];
            if (ITER == 0) {
                if (is64) {
                    const uint4* c1 = (const uint4*)x1 + pb;
                    const uint4* c2 = (const uint4*)x2 + pb;
                    #pragma unroll
                    for (int w = 0; w < 8; w++) { uint4 v = __ldcs(c1 + w); pk1[w] = v.x | (v.z << 16); }
                    #pragma unroll
                    for (int w = 0; w < 8; w++) { uint4 v = __ldcs(c2 + w); pk2[w] = v.x | (v.z << 16); }
                } else {
                    const uint4* c1 = (const uint4*)x1 + (pb >> 1);
                    const uint4* c2 = (const uint4*)x2 + (pb >> 1);
                    #pragma unroll
                    for (int w = 0; w < 4; w++) {
                        uint4 v = __ldcs(c1 + w);
                        pk1[2*w] = v.x | (v.y << 16); pk1[2*w+1] = v.z | (v.w << 16);
                    }
                    #pragma unroll
                    for (int w = 0; w < 4; w++) {
                        uint4 v = __ldcs(c2 + w);
                        pk2[2*w] = v.x | (v.y << 16); pk2[2*w+1] = v.z | (v.w << 16);
                    }
                }
                ((uint4*)(g_cx1 + pb))[0] = make_uint4(pk1[0], pk1[1], pk1[2], pk1[3]);
                ((uint4*)(g_cx1 + pb))[1] = make_uint4(pk1[4], pk1[5], pk1[6], pk1[7]);
                ((uint4*)(g_cx2 + pb))[0] = make_uint4(pk2[0], pk2[1], pk2[2], pk2[3]);
                ((uint4*)(g_cx2 + pb))[1] = make_uint4(pk2[4], pk2[5], pk2[6], pk2[7]);
            } else {
                const uint4* c1 = (const uint4*)(g_cx1 + pb);
                const uint4* c2 = (const uint4*)(g_cx2 + pb);
                uint4 q0 = __ldg(c1), q1 = __ldg(c1 + 1);   // all 4 LDGs up front
                uint4 r0 = __ldg(c2), r1 = __ldg(c2 + 1);
                pk1[0]=q0.x; pk1[1]=q0.y; pk1[2]=q0.z; pk1[3]=q0.w;
                pk1[4]=q1.x; pk1[5]=q1.y; pk1[6]=q1.z; pk1[7]=q1.w;
                pk2[0]=r0.x; pk2[1]=r0.y; pk2[2]=r0.z; pk2[3]=r0.w;
                pk2[4]=r1.x; pk2[5]=r1.y; pk2[6]=r1.z; pk2[7]=r1.w;
            }
            __half2 f1a, f1b, f2a, f2b;
            gath8(pk1, tabh, f1a, f1b);
            gath8(pk2, tabh, f2a, f2b);
            F1h[j*9 + nl] = make_uint2(*(unsigned*)&f1a, *(unsigned*)&f1b);
            float2 lo = __half22float2(f2a), hi = __half22float2(f2b);
            F2f[nl*65 + j] = make_float4(lo.x, lo.y, hi.x, hi.y);
            mbar_arrive(mb_full + 8*s);
        }
    } else {
        // ============ CONSUMER: bilinear + reduce + finalize =====================
        const int ctid = tid - NPROD;          // 0..511
        const int jj = ctid & 63;              // pi column
        const int nC = ctid >> 6;              // 0..7: n within chunk
        const int half = (ctid >> 5) & 1;
        const float p1 = pi1s[jj], p2 = pi2s[jj];
        for (int i = 0; ; i++) {
            const int s = i & 3, ks = i >> 2;
            mbar_wait(mb_full + 8*s, ks & 1);
            const int chunk = hdr[s];
            if (chunk >= NCHUNK) break;
            const int n0 = chunk * NPB;
            const uint2*  F1h = (const uint2*) (smem + OFF_STG + s*STG_BYTES);
            const float4* F2f = (const float4*)(smem + OFF_STG + s*STG_BYTES + STG_F2);

            ull mv01 = 0ull, mv23 = 0ull;
            const ulonglong2* row = (const ulonglong2*)(F2f + nC*65);
            #pragma unroll 8
            for (int kp = 0; kp < 32; kp++) {
                float2 pw = __half22float2(piPh[kp*64 + jj]);
                ull pwx = pack2(pw.x, pw.x);
                ull pwy = pack2(pw.y, pw.y);
                ulonglong2 U0 = row[2*kp], U1 = row[2*kp + 1];
                fma2(mv01, pwx, U0.x); fma2(mv23, pwx, U0.y);
                fma2(mv01, pwy, U1.x); fma2(mv23, pwy, U1.y);
            }
            uint2  hp  = F1h[jj*9 + nC];
            float4 f2v = F2f[nC*65 + jj];
            mbar_arrive(mb_empty + 8*s);   // stage reads done -> release early

            float2 ma  = unpack2(mv01), mb2 = unpack2(mv23);
            float2 f01 = __half22float2(*(__half2*)&hp.x);
            float2 f23 = __half22float2(*(__half2*)&hp.y);
            float4 c;
            c.x = p1*f01.x + p2*f2v.x - f01.x*ma.x;
            c.y = p1*f01.y + p2*f2v.y - f01.y*ma.y;
            c.z = p1*f23.x + p2*f2v.z - f23.x*mb2.x;
            c.w = p1*f23.y + p2*f2v.w - f23.y*mb2.y;
            #pragma unroll
            for (int off = 16; off > 0; off >>= 1) {
                c.x += __shfl_xor_sync(0xFFFFFFFFu, c.x, off);
                c.y += __shfl_xor_sync(0xFFFFFFFFu, c.y, off);
                c.z += __shfl_xor_sync(0xFFFFFFFFu, c.z, off);
                c.w += __shfl_xor_sync(0xFFFFFFFFu, c.w, off);
            }
            if (lane == 0) red4[s*16 + nC*2 + half] = c;
            asm volatile("bar.sync 2, %0;" :: "n"(NT - NPROD) : "memory");

            // finalize: a' = 1 - (1-a)(1-derived)
            if (ITER == 0) {
                if (ctid < NPB) {
                    const int n = n0 + ctid;
                    float4 d0 = red4[s*16 + ctid*2], d1 = red4[s*16 + ctid*2 + 1];
                    uint2 u = tabh[n];
                    float2 a01 = __half22float2(*(__half2*)&u.x);
                    float2 a23 = __half22float2(*(__half2*)&u.y);
                    __half2 h01 = __floats2half2_rn(
                        1.f - (1.f - a01.x) * (1.f - (d0.x + d1.x)),
                        1.f - (1.f - a01.y) * (1.f - (d0.y + d1.y)));
                    __half2 h23 = __floats2half2_rn(
                        1.f - (1.f - a23.x) * (1.f - (d0.z + d1.z)),
                        1.f - (1.f - a23.y) * (1.f - (d0.w + d1.w)));
                    g_tabB[n] = make_uint2(*(unsigned*)&h01, *(unsigned*)&h23);
                }
            } else {
                if (ctid < 4*NPB) {
                    const int b = ctid >> 3, nl = ctid & 7;
                    const int n = n0 + nl;
                    float dv = redf[s*64 + nl*8 + b] + redf[s*64 + nl*8 + 4 + b];
                    float av = __half2float(((const __half*)smem)[n*4 + b]);
                    out[b*NN + n] = 1.f - (1.f - av) * (1.f - dv);
                }
            }
        }
    }
}

// ---------------- launcher ----------------------------------------------------
extern "C" void kernel_launch(void* const* d_in, const int* in_sizes, int n_in,
                              void* d_out, int out_size) {
    const float* a0 = (const float*)d_in[0];
    const float* Wm = (const float*)d_in[1];
    const void*  x1 = d_in[2];
    const void*  x2 = d_in[3];
    float* out = (float*)d_out;

    cudaFuncSetAttribute(k_iter<0>, cudaFuncAttributeMaxDynamicSharedMemorySize, SMEM_TOTAL);
    cudaFuncSetAttribute(k_iter<1>, cudaFuncAttributeMaxDynamicSharedMemorySize, SMEM_TOTAL);

    k_iter<0><<<NBLK, NT, SMEM_TOTAL>>>(a0, Wm, x1, x2, out);  // raw X -> packed + tabB
    k_iter<1><<<NBLK, NT, SMEM_TOTAL>>>(a0, Wm, x1, x2, out);  // packed -> out
}

// round 12
// speedup vs baseline: 1.4024x; 1.4024x over previous
#include <cuda_runtime.h>
#include <cuda_fp16.h>
#include <cstdint>

#define NN 20000
#define MM 64
#define WL 8
#define NPAIRS (MM*NN*WL)      /* 10,240,000 pairs per X tensor */
#define NPB 16                 /* n's per chunk */
#define NCHUNK (NN/NPB)        /* 1250 */
#define NBLK 148               /* one block per SM */
#define NT 1024                /* 16 producer + 16 consumer warps */
#define NPROD 512
#define NCONS 512
#define NSTG 4

/* ---- stage: F1h [64][17] uint2 (8704 B) + F2f [16][67] float4 (17152 B) ---- */
#define STG_F2    8704
#define STG_BYTES 25856

/* ---- shared memory layout (bytes) ---- */
#define OFF_STG   (NN*4)                      /* 80000 : u8 table (4 batches/word) */
#define OFF_PIP   (OFF_STG + NSTG*STG_BYTES)  /* 183424 : piP half2[32*64]     */
#define OFF_P12   (OFF_PIP + 8192)            /* 191616 : pi1, pi2             */
#define OFF_RED   (OFF_P12 + 512)             /* 192128 : float4[4][16][2]     */
#define OFF_CTL   (OFF_RED + 2048)            /* 194176 : hdr[4] + 8 mbarriers */
#define SMEM_TOTAL (OFF_CTL + 96)             /* 194272 */

#define FS (1.0f/(255.0f*255.0f))

typedef unsigned long long ull;

// ---------------- device scratch (static) ------------------------------------
__device__ unsigned g_cx1[NPAIRS];   // packed (i0 | i1<<16)
__device__ unsigned g_cx2[NPAIRS];
__device__ unsigned g_tabB8[NN];     // a1 as 4 x u8 (gather table for iter 1)
__device__ float4   g_tabA32[NN];    // a1 exact f32 (finalize sidecar)
__device__ int      g_tick[2] = {0, 0};

// ---------------- small helpers ----------------------------------------------
__device__ __forceinline__ unsigned s2u(const void* p) {
    return (unsigned)__cvta_generic_to_shared(p);
}
__device__ __forceinline__ void mbar_init(unsigned a, unsigned cnt) {
    asm volatile("mbarrier.init.shared.b64 [%0], %1;" :: "r"(a), "r"(cnt) : "memory");
}
__device__ __forceinline__ void mbar_arrive(unsigned a) {
    asm volatile("mbarrier.arrive.release.cta.shared::cta.b64 _, [%0];" :: "r"(a) : "memory");
}
__device__ __forceinline__ void mbar_wait(unsigned a, unsigned parity) {
    asm volatile(
        "{\n\t.reg .pred P;\n\t"
        "WL_%=:\n\t"
        "mbarrier.try_wait.parity.acquire.cta.shared::cta.b64 P, [%0], %1, 0x989680;\n\t"
        "@P bra.uni WD_%=;\n\t"
        "bra.uni WL_%=;\n\t"
        "WD_%=:\n\t}"
        :: "r"(a), "r"(parity) : "memory");
}
__device__ __forceinline__ ull pack2(float lo, float hi) {
    ull r; asm("mov.b64 %0, {%1, %2};" : "=l"(r) : "f"(lo), "f"(hi)); return r;
}
__device__ __forceinline__ float2 unpack2(ull v) {
    float2 f; asm("mov.b64 {%0, %1}, %2;" : "=f"(f.x), "=f"(f.y) : "l"(v)); return f;
}
__device__ __forceinline__ void fma2(ull& d, ull a, ull b) {
    asm("fma.rn.f32x2 %0, %1, %2, %0;" : "+l"(d) : "l"(a), "l"(b));
}
// u8x4 word -> exact half2 of bytes {b0,b1} / {b2,b3} (PRMT exponent-offset trick)
__device__ __forceinline__ __half2 h1024() {
    unsigned u = 0x64006400u; return *(__half2*)&u;
}
__device__ __forceinline__ __half2 cvtlo(unsigned A) {
    unsigned r = __byte_perm(A, 0x64646464u, 0x4140);
    return __hsub2(*(__half2*)&r, h1024());
}
__device__ __forceinline__ __half2 cvthi(unsigned A) {
    unsigned r = __byte_perm(A, 0x64646464u, 0x4342);
    return __hsub2(*(__half2*)&r, h1024());
}
// gather: 8 independent products, max tree (values are raw byte products, >=0)
__device__ __forceinline__ void gath8(const unsigned* pk, const unsigned* __restrict__ tab,
                                      __half2& ga, __half2& gb) {
    __half2 px[8], py[8];
    #pragma unroll
    for (int w = 0; w < 8; w++) {
        unsigned A = tab[pk[w] & 0xFFFFu];
        unsigned B = tab[pk[w] >> 16];
        px[w] = __hmul2(cvtlo(A), cvtlo(B));
        py[w] = __hmul2(cvthi(A), cvthi(B));
    }
    #pragma unroll
    for (int s = 4; s > 0; s >>= 1)
        #pragma unroll
        for (int w = 0; w < s; w++) {
            px[w] = __hmax2(px[w], px[w + s]);
            py[w] = __hmax2(py[w], py[w + s]);
        }
    ga = px[0]; gb = py[0];
}
__device__ __forceinline__ unsigned q8x4(float a, float b, float c, float d) {
    unsigned r =  __float2uint_rn(__saturatef(a) * 255.f);
    r |= __float2uint_rn(__saturatef(b) * 255.f) << 8;
    r |= __float2uint_rn(__saturatef(c) * 255.f) << 16;
    r |= __float2uint_rn(__saturatef(d) * 255.f) << 24;
    return r;
}

// ---------------- main iteration kernel --------------------------------------
template<int ITER>
__global__ void __launch_bounds__(NT, 1) k_iter(const float* __restrict__ a0,
                                                const float* __restrict__ Wm,
                                                const void* __restrict__ x1,
                                                const void* __restrict__ x2,
                                                float* __restrict__ out) {
    extern __shared__ char smem[];
    unsigned* tabu = (unsigned*)smem;                 // [NN] u8x4
    __half2*  piPh = (__half2*)(smem + OFF_PIP);      // [32*64]
    float*    pi1s = (float*) (smem + OFF_P12);
    float*    pi2s = pi1s + MM;
    float4*   red4 = (float4*)(smem + OFF_RED);       // [4][16][2]
    float*    redf = (float*) (smem + OFF_RED);
    volatile int* hdr = (volatile int*)(smem + OFF_CTL);  // [4]
    const unsigned mb_full  = s2u(smem + OFF_CTL + 16);   // 4 x 8B
    const unsigned mb_empty = s2u(smem + OFF_CTL + 48);   // 4 x 8B

    const int tid  = threadIdx.x;
    const int warp = tid >> 5, lane = tid & 31;

    if (blockIdx.x == 0 && tid == 0) g_tick[ITER ^ 1] = 0;
    if (tid < NSTG) {
        mbar_init(mb_full  + 8*tid, NPROD);
        mbar_init(mb_empty + 8*tid, NCONS);
    }

    // ===== preamble: u8 4-batch a-table =====
    if (ITER == 0) {
        for (int i = tid; i < NN; i += NT)
            tabu[i] = q8x4(__ldg(a0 + i), __ldg(a0 + NN + i),
                           __ldg(a0 + 2*NN + i), __ldg(a0 + 3*NN + i));
    } else {
        for (int i = tid; i < NN; i += NT) tabu[i] = g_tabB8[i];
    }

    // ===== preamble: softmax over 64x64 W (scratch = stage area, pre-roles) =====
    {
        float* sp = (float*)(smem + OFF_STG);
        float v4[4];
        float lm = -1e30f;
        #pragma unroll
        for (int t = 0; t < 4; t++) {
            float v = __ldg(Wm + tid + t*NT);
            v4[t] = v;
            lm = fmaxf(lm, v);
        }
        #pragma unroll
        for (int off = 16; off > 0; off >>= 1)
            lm = fmaxf(lm, __shfl_xor_sync(0xFFFFFFFFu, lm, off));
        if (lane == 0) redf[warp] = lm;
        __syncthreads();
        float m = -1e30f;
        #pragma unroll
        for (int w = 0; w < 32; w++) m = fmaxf(m, redf[w]);
        __syncthreads();
        float ls = 0.f;
        #pragma unroll
        for (int t = 0; t < 4; t++) {
            float e = expf(v4[t] - m);
            sp[tid + t*NT] = e;
            ls += e;
        }
        #pragma unroll
        for (int off = 16; off > 0; off >>= 1)
            ls += __shfl_xor_sync(0xFFFFFFFFu, ls, off);
        if (lane == 0) redf[32 + warp] = ls;
        __syncthreads();
        float tot = 0.f;
        #pragma unroll
        for (int w = 0; w < 32; w++) tot += redf[32 + w];
        const float inv = 1.f / tot;

        for (int i = tid; i < 2048; i += NT) {
            int kp = i >> 6, j = i & 63;
            piPh[i] = __floats2half2_rn(sp[j*MM + 2*kp] * inv, sp[j*MM + 2*kp + 1] * inv);
        }
        if (tid < MM) {
            float s = 0.f;
            #pragma unroll 16
            for (int k = 0; k < MM; k++) s += sp[tid*MM + k];
            pi1s[tid] = s * inv;
        } else if (tid < 2*MM) {
            int k = tid - MM;
            float s = 0.f;
            #pragma unroll 16
            for (int j = 0; j < MM; j++) s += sp[j*MM + k];
            pi2s[k] = s * inv;
        }
    }

    // ===== preamble: dtype probe (iter 0 only) =====
    int is64 = 0;
    if (ITER == 0) {
        const unsigned* x1u = (const unsigned*)x1;
        int nz = (x1u[2*tid + 1] != 0u) | (x1u[2*(tid + NT) + 1] != 0u);
        is64 = !__syncthreads_or(nz);
    }
    __syncthreads();   // scratch dead; tab/piP/pi/mbar visible to all

    int* tick = &g_tick[ITER];

    if (tid < NPROD) {
        // ============ PRODUCER: 2 (j, nl) tasks per thread per chunk ============
        for (int i = 0; ; i++) {
            const int s = i & 3, ks = i >> 2;
            if (i >= NSTG) mbar_wait(mb_empty + 8*s, (ks - 1) & 1);
            if (tid == 0) hdr[s] = atomicAdd(tick, 1);
            asm volatile("bar.sync 1, %0;" :: "n"(NPROD) : "memory");
            const int chunk = hdr[s];
            if (chunk >= NCHUNK) { mbar_arrive(mb_full + 8*s); break; }
            const int n0 = chunk * NPB;
            uint2*  F1h = (uint2*) (smem + OFF_STG + s*STG_BYTES);
            float4* F2f = (float4*)(smem + OFF_STG + s*STG_BYTES + STG_F2);

            #pragma unroll
            for (int p = 0; p < 2; p++) {
                const int t  = p*NPROD + tid;
                const int j  = t >> 4;
                const int nl = t & 15;
                const size_t pb = ((size_t)j * NN + n0 + nl) * WL;
                unsigned pk1[8], pk2[8];
                if (ITER == 0) {
                    if (is64) {
                        const uint4* c1 = (const uint4*)x1 + pb;
                        const uint4* c2 = (const uint4*)x2 + pb;
                        #pragma unroll
                        for (int w = 0; w < 8; w++) { uint4 v = __ldcs(c1 + w); pk1[w] = v.x | (v.z << 16); }
                        #pragma unroll
                        for (int w = 0; w < 8; w++) { uint4 v = __ldcs(c2 + w); pk2[w] = v.x | (v.z << 16); }
                    } else {
                        const uint4* c1 = (const uint4*)x1 + (pb >> 1);
                        const uint4* c2 = (const uint4*)x2 + (pb >> 1);
                        #pragma unroll
                        for (int w = 0; w < 4; w++) {
                            uint4 v = __ldcs(c1 + w);
                            pk1[2*w] = v.x | (v.y << 16); pk1[2*w+1] = v.z | (v.w << 16);
                        }
                        #pragma unroll
                        for (int w = 0; w < 4; w++) {
                            uint4 v = __ldcs(c2 + w);
                            pk2[2*w] = v.x | (v.y << 16); pk2[2*w+1] = v.z | (v.w << 16);
                        }
                    }
                    ((uint4*)(g_cx1 + pb))[0] = make_uint4(pk1[0], pk1[1], pk1[2], pk1[3]);
                    ((uint4*)(g_cx1 + pb))[1] = make_uint4(pk1[4], pk1[5], pk1[6], pk1[7]);
                    ((uint4*)(g_cx2 + pb))[0] = make_uint4(pk2[0], pk2[1], pk2[2], pk2[3]);
                    ((uint4*)(g_cx2 + pb))[1] = make_uint4(pk2[4], pk2[5], pk2[6], pk2[7]);
                } else {
                    const uint4* c1 = (const uint4*)(g_cx1 + pb);
                    const uint4* c2 = (const uint4*)(g_cx2 + pb);
                    uint4 q0 = __ldg(c1), q1 = __ldg(c1 + 1);
                    uint4 r0 = __ldg(c2), r1 = __ldg(c2 + 1);
                    pk1[0]=q0.x; pk1[1]=q0.y; pk1[2]=q0.z; pk1[3]=q0.w;
                    pk1[4]=q1.x; pk1[5]=q1.y; pk1[6]=q1.z; pk1[7]=q1.w;
                    pk2[0]=r0.x; pk2[1]=r0.y; pk2[2]=r0.z; pk2[3]=r0.w;
                    pk2[4]=r1.x; pk2[5]=r1.y; pk2[6]=r1.z; pk2[7]=r1.w;
                }
                __half2 f1a, f1b, f2a, f2b;
                gath8(pk1, tabu, f1a, f1b);
                gath8(pk2, tabu, f2a, f2b);
                F1h[j*17 + nl] = make_uint2(*(unsigned*)&f1a, *(unsigned*)&f1b);  // raw products
                float2 lo = __half22float2(f2a), hi = __half22float2(f2b);
                F2f[nl*67 + j] = make_float4(lo.x*FS, lo.y*FS, hi.x*FS, hi.y*FS); // true units
            }
            mbar_arrive(mb_full + 8*s);
        }
    } else {
        // ============ CONSUMER: bilinear + reduce + finalize =====================
        const int ctid = tid - NPROD;          // 0..511
        const int jj = ctid & 63;              // pi column
        const int g8 = ctid >> 6;              // 0..7 -> n = g8, g8+8
        const int half = (ctid >> 5) & 1;
        const float p1 = pi1s[jj], p2 = pi2s[jj];
        for (int i = 0; ; i++) {
            const int s = i & 3, ks = i >> 2;
            mbar_wait(mb_full + 8*s, ks & 1);
            const int chunk = hdr[s];
            if (chunk >= NCHUNK) break;
            const int n0 = chunk * NPB;
            const uint2*  F1h = (const uint2*) (smem + OFF_STG + s*STG_BYTES);
            const float4* F2f = (const float4*)(smem + OFF_STG + s*STG_BYTES + STG_F2);

            ull mv00 = 0ull, mv01 = 0ull, mv10 = 0ull, mv11 = 0ull;   // [n][b01/b23]
            const ulonglong2* fbA = (const ulonglong2*)(F2f + g8*67);
            const ulonglong2* fbB = (const ulonglong2*)(F2f + (g8+8)*67);
            #pragma unroll 8
            for (int kp = 0; kp < 32; kp++) {
                float2 pw = __half22float2(piPh[kp*64 + jj]);
                ull pwx = pack2(pw.x, pw.x);
                ull pwy = pack2(pw.y, pw.y);
                ulonglong2 A0 = fbA[2*kp], B0 = fbA[2*kp + 1];
                ulonglong2 A1 = fbB[2*kp], B1 = fbB[2*kp + 1];
                fma2(mv00, pwx, A0.x); fma2(mv01, pwx, A0.y);
                fma2(mv00, pwy, B0.x); fma2(mv01, pwy, B0.y);
                fma2(mv10, pwx, A1.x); fma2(mv11, pwx, A1.y);
                fma2(mv10, pwy, B1.x); fma2(mv11, pwy, B1.y);
            }
            uint2  hpA  = F1h[jj*17 + g8];
            uint2  hpB  = F1h[jj*17 + g8 + 8];
            float4 f2vA = F2f[g8*67 + jj];
            float4 f2vB = F2f[(g8+8)*67 + jj];
            mbar_arrive(mb_empty + 8*s);   // stage reads done -> release early

            #pragma unroll
            for (int r = 0; r < 2; r++) {
                const int n = g8 + r*8;
                float2 ma = unpack2(r ? mv10 : mv00);
                float2 mb = unpack2(r ? mv11 : mv01);
                uint2  hp  = r ? hpB : hpA;
                float4 f2v = r ? f2vB : f2vA;
                float2 f01 = __half22float2(*(__half2*)&hp.x);
                float2 f23 = __half22float2(*(__half2*)&hp.y);
                float4 c;   // c = FS*f1raw*(p1 - mv) + p2*F2true
                c.x = FS*f01.x*(p1 - ma.x) + p2*f2v.x;
                c.y = FS*f01.y*(p1 - ma.y) + p2*f2v.y;
                c.z = FS*f23.x*(p1 - mb.x) + p2*f2v.z;
                c.w = FS*f23.y*(p1 - mb.y) + p2*f2v.w;
                #pragma unroll
                for (int off = 16; off > 0; off >>= 1) {
                    c.x += __shfl_xor_sync(0xFFFFFFFFu, c.x, off);
                    c.y += __shfl_xor_sync(0xFFFFFFFFu, c.y, off);
                    c.z += __shfl_xor_sync(0xFFFFFFFFu, c.z, off);
                    c.w += __shfl_xor_sync(0xFFFFFFFFu, c.w, off);
                }
                if (lane == 0) red4[s*32 + n*2 + half] = c;
            }
            asm volatile("bar.sync 2, %0;" :: "n"(NCONS) : "memory");

            // finalize: a' = 1 - (1-a)(1-derived)
            if (ITER == 0) {
                if (ctid < NPB) {
                    const int n = n0 + ctid;
                    float4 d0 = red4[s*32 + ctid*2], d1 = red4[s*32 + ctid*2 + 1];
                    unsigned u = tabu[n];
                    float4 an;
                    an.x = 1.f - (1.f - (float)((u      ) & 0xFF)*(1.f/255.f)) * (1.f - (d0.x + d1.x));
                    an.y = 1.f - (1.f - (float)((u >>  8) & 0xFF)*(1.f/255.f)) * (1.f - (d0.y + d1.y));
                    an.z = 1.f - (1.f - (float)((u >> 16) & 0xFF)*(1.f/255.f)) * (1.f - (d0.z + d1.z));
                    an.w = 1.f - (1.f - (float)((u >> 24)       )*(1.f/255.f)) * (1.f - (d0.w + d1.w));
                    g_tabB8[n]  = q8x4(an.x, an.y, an.z, an.w);
                    g_tabA32[n] = an;
                }
            } else {
                if (ctid < 4*NPB) {
                    const int b = ctid >> 4, nl = ctid & 15;
                    const int n = n0 + nl;
                    float dv = redf[s*128 + nl*8 + b] + redf[s*128 + nl*8 + 4 + b];
                    float av = ((const float*)g_tabA32)[n*4 + b];   // exact f32 a1
                    out[b*NN + n] = 1.f - (1.f - av) * (1.f - dv);
                }
            }
        }
    }
}

// ---------------- launcher ----------------------------------------------------
extern "C" void kernel_launch(void* const* d_in, const int* in_sizes, int n_in,
                              void* d_out, int out_size) {
    const float* a0 = (const float*)d_in[0];
    const float* Wm = (const float*)d_in[1];
    const void*  x1 = d_in[2];
    const void*  x2 = d_in[3];
    float* out = (float*)d_out;

    cudaFuncSetAttribute(k_iter<0>, cudaFuncAttributeMaxDynamicSharedMemorySize, SMEM_TOTAL);
    cudaFuncSetAttribute(k_iter<1>, cudaFuncAttributeMaxDynamicSharedMemorySize, SMEM_TOTAL);

    k_iter<0><<<NBLK, NT, SMEM_TOTAL>>>(a0, Wm, x1, x2, out);  // raw X -> packed + u8/f32 a1
    k_iter<1><<<NBLK, NT, SMEM_TOTAL>>>(a0, Wm, x1, x2, out);  // packed -> out
}